// round 14
// baseline (speedup 1.0000x reference)
#include <cuda_runtime.h>
#include <cuda_fp16.h>
#include <math.h>
#include <stdint.h>

#define BB 256
#define HH 1024
#define TT 128
#define FF 512

#define NCTA 128
#define NGRP 8
#define GRPSZ 16

// ---- scan kernel tiling: CTA 64(M) x 128(N), KC=64/stage, 3 stages ----
#define KC 64
#define SC_NSTG 3
#define SC_OFF_A 0
#define SC_OFF_B 8192
#define SC_STAGE 24576
#define SC_SMEM  (SC_NSTG * SC_STAGE)     // 73728

// ---- dense kernel tiling: KC=32, 4 stages ----
#define DKC 32
#define D_OFF_A  0
#define D_OFF_B  4096
#define D_STAGE  12288
#define D_SMEM   (4 * D_STAGE)            // 49152

// ---------------- device scratch ----------------------------------------------
__device__ __half g_wsum[4096 * 1024];      // [n=4j+g][k]
__device__ __half g_wcat[4096 * 2048];      // t=0: K = [W;U]
__device__ __half g_wd[512 * 1024];         // [f][k]
__device__ __half g_xcat[256 * 2048];       // [b][x0,h0]
__device__ __half g_xa[256 * 1024];         // ping
__device__ __half g_xb[256 * 1024];         // pong
__device__ __half g_seq[(size_t)BB * TT * HH];
__device__ unsigned g_bar_l0[NGRP * 32];    // group counters, 128B apart
__device__ unsigned g_bar_root;
__device__ unsigned g_bar_gen;

// ---------------- helpers -----------------------------------------------------
__device__ __forceinline__ uint32_t smem_u32(const void* p) {
    uint32_t a;
    asm("{ .reg .u64 t; cvta.to.shared.u64 t, %1; cvt.u32.u64 %0, t; }" : "=r"(a) : "l"(p));
    return a;
}
__device__ __forceinline__ uint32_t sw64(uint32_t o)  { return o ^ ((o >> 3) & 0x30); }
__device__ __forceinline__ uint32_t sw128(uint32_t o) { return o ^ ((o >> 3) & 0x70); }
__device__ __forceinline__ float tanh_(float x) {
    float y;
    asm("tanh.approx.f32 %0, %1;" : "=f"(y) : "f"(x));
    return y;
}
__device__ __forceinline__ float sigm(float x) {
    return 0.5f * tanh_(0.5f * x) + 0.5f;
}

#define CP_ASYNC16(sm, gp) \
    asm volatile("cp.async.cg.shared.global [%0], [%1], 16;" :: "r"(sm), "l"(gp) : "memory")
#define CP_COMMIT() asm volatile("cp.async.commit_group;" ::: "memory")
template <int N>
__device__ __forceinline__ void cp_wait() {
    asm volatile("cp.async.wait_group %0;" :: "n"(N) : "memory");
}

__device__ __forceinline__ void ldsm4(uint32_t* r, uint32_t addr) {
    asm volatile("ldmatrix.sync.aligned.m8n8.x4.shared.b16 {%0,%1,%2,%3}, [%4];"
                 : "=r"(r[0]), "=r"(r[1]), "=r"(r[2]), "=r"(r[3]) : "r"(addr));
}
__device__ __forceinline__ void mma16816(float* c, const uint32_t* a, uint32_t b0, uint32_t b1) {
    asm volatile("mma.sync.aligned.m16n8k16.row.col.f32.f16.f16.f32 "
                 "{%0,%1,%2,%3},{%4,%5,%6,%7},{%8,%9},{%0,%1,%2,%3};"
                 : "+f"(c[0]), "+f"(c[1]), "+f"(c[2]), "+f"(c[3])
                 : "r"(a[0]), "r"(a[1]), "r"(a[2]), "r"(a[3]), "r"(b0), "r"(b1));
}

// ---------------- hierarchical split grid barrier -----------------------------
// 8 group counters (16 CTAs each, 128B-padded) -> 1 root -> generation word.
__device__ __forceinline__ void bar_arrive(int grp) {
    __syncthreads();                          // CTA's stores ordered before arrival
    if (threadIdx.x == 0) {
        __threadfence();                      // release
        unsigned a = atomicAdd(&g_bar_l0[grp * 32], 1u);
        if (a == GRPSZ - 1) {
            atomicExch(&g_bar_l0[grp * 32], 0u);   // reset own group
            unsigned r = atomicAdd(&g_bar_root, 1u);
            if (r == NGRP - 1) {
                atomicExch(&g_bar_root, 0u);
                __threadfence();
                atomicAdd(&g_bar_gen, 1u);    // release the pack
            }
        }
    }
}
__device__ __forceinline__ void bar_wait(unsigned target) {
    if (threadIdx.x == 0) {
        volatile unsigned* pg = &g_bar_gen;
        while (*pg < target) {}
        __threadfence();                      // acquire
    }
    __syncthreads();
}

// ---------------- persistent LSTM scan kernel ---------------------------------
// grid 128 CTAs = 32 n-tiles (Tn=128, gate-interleaved) x 4 m-tiles (Tm=64).
// KC=64 chunks; split hierarchical barrier with B-prefetch during the wait.
#define HSPAD 36   // halves per staged h row (32 data + 4 pad)

__global__ __launch_bounds__(256)
void lstm_scan(const __half* __restrict__ xcat, const __half* __restrict__ wcat,
               const __half* __restrict__ wsum,
               const float* __restrict__ bias, const float* __restrict__ c0,
               __half* __restrict__ x0buf, __half* __restrict__ x1buf) {
    extern __shared__ char smem[];
    const uint32_t sbase = smem_u32(smem);
    __half* HS = reinterpret_cast<__half*>(smem);   // staging, aliases stage 0 A-region

    const int ntile = blockIdx.x & 31;
    const int mtile = blockIdx.x >> 5;
    const int grp = blockIdx.x >> 4;               // 8 groups of 16
    const int am0 = mtile * 64;
    const int bn0 = ntile * 128;
    const int j0 = ntile * 32;

    const int tid = threadIdx.x;
    const int lane = tid & 31, wid = tid >> 5;
    const int wm = wid & 1, wn = wid >> 1;
    const bool odd = lane & 1;
    const int lrow = lane & 15;
    const int lkb = (lane >> 4) * 16;

    int bmap[2], jmap[4];
#pragma unroll
    for (int mi = 0; mi < 2; ++mi)
        bmap[mi] = am0 + wm * 32 + mi * 16 + (lane >> 2) + (odd ? 8 : 0);
#pragma unroll
    for (int nt = 0; nt < 4; ++nt)
        jmap[nt] = j0 + wn * 8 + nt * 2 + ((lane & 3) >> 1);

    float b_i[4], b_f[4], b_g[4], b_o[4];
#pragma unroll
    for (int nt = 0; nt < 4; ++nt) {
        b_i[nt] = bias[jmap[nt]];
        b_f[nt] = bias[HH + jmap[nt]];
        b_g[nt] = bias[2 * HH + jmap[nt]];
        b_o[nt] = bias[3 * HH + jmap[nt]];
    }
    float creg[2][4];
#pragma unroll
    for (int mi = 0; mi < 2; ++mi)
#pragma unroll
        for (int nt = 0; nt < 4; ++nt)
            creg[mi][nt] = c0[bmap[mi] * HH + jmap[nt]];

    auto issueA = [&](const __half* A, int ldk, int s, int c) {
        const uint32_t st = sbase + s * SC_STAGE;
        const int k0 = c * KC;
#pragma unroll
        for (int it = 0; it < 2; ++it) {
            const int g = it * 256 + tid;
            const int r = g >> 3, q = g & 7;
            CP_ASYNC16(st + SC_OFF_A + sw128((uint32_t)(r * 128 + q * 16)),
                       A + (size_t)(am0 + r) * ldk + k0 + q * 8);
        }
        CP_COMMIT();
    };
    auto issueB = [&](const __half* B, int ldk, int s, int c) {
        const uint32_t st = sbase + s * SC_STAGE;
        const int k0 = c * KC;
#pragma unroll
        for (int it = 0; it < 4; ++it) {
            const int g = it * 256 + tid;
            const int r = g >> 3, q = g & 7;
            CP_ASYNC16(st + SC_OFF_B + sw128((uint32_t)(r * 128 + q * 16)),
                       B + (size_t)(bn0 + r) * ldk + k0 + q * 8);
        }
        CP_COMMIT();
    };
    auto issueAB = [&](const __half* A, const __half* B, int ldk, int s, int c) {
        const uint32_t st = sbase + s * SC_STAGE;
        const int k0 = c * KC;
#pragma unroll
        for (int it = 0; it < 2; ++it) {
            const int g = it * 256 + tid;
            const int r = g >> 3, q = g & 7;
            CP_ASYNC16(st + SC_OFF_A + sw128((uint32_t)(r * 128 + q * 16)),
                       A + (size_t)(am0 + r) * ldk + k0 + q * 8);
        }
#pragma unroll
        for (int it = 0; it < 4; ++it) {
            const int g = it * 256 + tid;
            const int r = g >> 3, q = g & 7;
            CP_ASYNC16(st + SC_OFF_B + sw128((uint32_t)(r * 128 + q * 16)),
                       B + (size_t)(bn0 + r) * ldk + k0 + q * 8);
        }
        CP_COMMIT();
    };
    auto mma_stage = [&](int s, float C[2][4][4]) {
        const uint32_t st = sbase + s * SC_STAGE;
#pragma unroll
        for (int h = 0; h < 4; ++h) {
            uint32_t ah[2][4], bh[2][4];
#pragma unroll
            for (int mi = 0; mi < 2; ++mi)
                ldsm4(ah[mi], st + SC_OFF_A +
                      sw128((uint32_t)((wm * 32 + mi * 16 + lrow) * 128 + h * 32 + lkb)));
#pragma unroll
            for (int nj = 0; nj < 2; ++nj)
                ldsm4(bh[nj], st + SC_OFF_B +
                      sw128((uint32_t)((wn * 32 + nj * 16 + lrow) * 128 + h * 32 + lkb)));
#pragma unroll
            for (int mi = 0; mi < 2; ++mi)
#pragma unroll
                for (int nt = 0; nt < 4; ++nt) {
                    const int gsel = nt >> 1, ssel = nt & 1;
                    mma16816(C[mi][nt], ah[mi], bh[gsel][ssel], bh[gsel][ssel + 2]);
                }
        }
    };

    const unsigned G = *(volatile unsigned*)&g_bar_gen;
    unsigned tgt = G;

    for (int t = 0; t < TT; ++t) {
        __half* xnext = (t & 1) ? x1buf : x0buf;

        float C[2][4][4];
#pragma unroll
        for (int a = 0; a < 2; ++a)
#pragma unroll
            for (int bq = 0; bq < 4; ++bq)
#pragma unroll
                for (int d = 0; d < 4; ++d) C[a][bq][d] = 0.0f;

        if (t == 0) {
            const int nch = 2048 / KC;   // 32
            issueAB(xcat, wcat, 2048, 0, 0);
            issueAB(xcat, wcat, 2048, 1, 1);
            for (int c = 0; c < nch; ++c) {
                if (c < nch - 1) cp_wait<1>(); else cp_wait<0>();
                __syncthreads();
                mma_stage(c % SC_NSTG, C);
                if (c + 2 < nch) issueAB(xcat, wcat, 2048, (c + 2) % SC_NSTG, c + 2);
            }
        } else {
            const __half* A = (t & 1) ? x0buf : x1buf;
            const int nch = HH / KC;     // 16
            // B chunks 0,1 prefetched during the barrier wait; add A now.
            issueA(A, HH, 0, 0);
            issueA(A, HH, 1, 1);
            for (int c = 0; c < nch; ++c) {
                if (c < nch - 1) cp_wait<1>(); else cp_wait<0>();
                __syncthreads();
                mma_stage(c % SC_NSTG, C);
                if (c + 2 < nch) issueAB(A, wsum, HH, (c + 2) % SC_NSTG, c + 2);
            }
        }
        __syncthreads();   // all stages consumed before HS reuse

        // epilogue: gates, c in registers, h -> smem staging
#pragma unroll
        for (int mi = 0; mi < 2; ++mi)
#pragma unroll
            for (int nt = 0; nt < 4; ++nt) {
                float* c = C[mi][nt];
                const float t0 = __shfl_xor_sync(0xFFFFFFFFu, c[0], 1);
                const float t1 = __shfl_xor_sync(0xFFFFFFFFu, c[1], 1);
                const float t2 = __shfl_xor_sync(0xFFFFFFFFu, c[2], 1);
                const float t3 = __shfl_xor_sync(0xFFFFFFFFu, c[3], 1);
                float zi, zf, zg, zo;
                if (!odd) { zi = c[0]; zf = c[1]; zg = t0; zo = t1; }
                else      { zi = t2;  zf = t3;  zg = c[2]; zo = c[3]; }
                zi += b_i[nt]; zf += b_f[nt]; zg += b_g[nt]; zo += b_o[nt];
                const float cn = sigm(zf) * creg[mi][nt] + sigm(zi) * tanh_(zg);
                const float hn = sigm(zo) * tanh_(cn);
                creg[mi][nt] = cn;
                HS[(bmap[mi] - am0) * HSPAD + (jmap[nt] - j0)] = __float2half(hn);
            }
        __syncthreads();

        // coalesced copy-out: 64 rows x 64B
        {
            const int row = tid >> 2, q = tid & 3;
            const uint32_t* src = reinterpret_cast<const uint32_t*>(HS + row * HSPAD) + q * 4;
            uint4 v;
            v.x = src[0]; v.y = src[1]; v.z = src[2]; v.w = src[3];
            const int b = am0 + row;
            *reinterpret_cast<uint4*>(xnext + (size_t)b * HH + j0 + q * 8) = v;
            *reinterpret_cast<uint4*>(g_seq + ((size_t)b * TT + t) * HH + j0 + q * 8) = v;
        }

        if (t < TT - 1) {
            ++tgt;
            bar_arrive(grp);                      // includes __syncthreads
            issueB(wsum, HH, 0, 0);               // prefetch next step's B during wait
            issueB(wsum, HH, 1, 1);               // (HS region untouched: B at +8KB)
            bar_wait(tgt);
        }
    }
}

// ---------------- dense emission (64x128, KC=32) -------------------------------
__device__ __forceinline__ void d_issue(uint32_t sbase, int s, int c,
                                        const __half* A, int am0,
                                        const __half* B, int bn0, int tid) {
    const uint32_t st = sbase + s * D_STAGE;
    const int k0 = c * DKC;
    const int ar = tid >> 2, ac = tid & 3;
    CP_ASYNC16(st + D_OFF_A + sw64((uint32_t)(ar * 64 + ac * 16)),
               A + (size_t)(am0 + ar) * HH + k0 + ac * 8);
#pragma unroll
    for (int it = 0; it < 2; ++it) {
        const int idx = it * 256 + tid;
        const int br = idx >> 2, bc = idx & 3;
        CP_ASYNC16(st + D_OFF_B + sw64((uint32_t)(br * 64 + bc * 16)),
                   B + (size_t)(bn0 + br) * HH + k0 + bc * 8);
    }
    CP_COMMIT();
}

__global__ __launch_bounds__(256)
void dense_mma(const float* __restrict__ bd, float* __restrict__ out) {
    extern __shared__ char smem[];
    const uint32_t sbase = smem_u32(smem);
    const int tid = threadIdx.x;
    const int lane = tid & 31, wid = tid >> 5;
    const int wm = wid & 1, wn = wid >> 1;
    const int lrow = lane & 15;
    const int lkb = (lane >> 4) * 16;

    float C[2][4][4];
#pragma unroll
    for (int a = 0; a < 2; ++a)
#pragma unroll
        for (int bq = 0; bq < 4; ++bq)
#pragma unroll
            for (int d = 0; d < 4; ++d) C[a][bq][d] = 0.0f;

    const int am0 = blockIdx.y * 64;
    const int bn0 = blockIdx.x * 128;
    const int nch = HH / DKC;

    d_issue(sbase, 0, 0, g_seq, am0, g_wd, bn0, tid);
    d_issue(sbase, 1, 1, g_seq, am0, g_wd, bn0, tid);
    d_issue(sbase, 2, 2, g_seq, am0, g_wd, bn0, tid);

    for (int c = 0; c < nch; ++c) {
        const int s = c & 3;
        if (c < nch - 2)       cp_wait<2>();
        else if (c == nch - 2) cp_wait<1>();
        else                   cp_wait<0>();
        __syncthreads();
        const uint32_t st = sbase + s * D_STAGE;
#pragma unroll
        for (int h = 0; h < 2; ++h) {
            uint32_t ah[2][4], bh[2][4];
#pragma unroll
            for (int mi = 0; mi < 2; ++mi)
                ldsm4(ah[mi], st + D_OFF_A + sw64((uint32_t)((wm * 32 + mi * 16 + lrow) * 64 + h * 32 + lkb)));
#pragma unroll
            for (int nj = 0; nj < 2; ++nj)
                ldsm4(bh[nj], st + D_OFF_B + sw64((uint32_t)((wn * 32 + nj * 16 + lrow) * 64 + h * 32 + lkb)));
#pragma unroll
            for (int mi = 0; mi < 2; ++mi)
#pragma unroll
                for (int nt = 0; nt < 4; ++nt) {
                    const int gsel = nt >> 1, ssel = nt & 1;
                    mma16816(C[mi][nt], ah[mi], bh[gsel][ssel], bh[gsel][ssel + 2]);
                }
        }
        if (c + 3 < nch)
            d_issue(sbase, (c + 3) & 3, c + 3, g_seq, am0, g_wd, bn0, tid);
    }

#pragma unroll
    for (int mi = 0; mi < 2; ++mi)
#pragma unroll
        for (int nt = 0; nt < 4; ++nt) {
            const float* c = C[mi][nt];
            const int n = bn0 + wn * 32 + nt * 8 + 2 * (lane & 3);
            const int r = am0 + wm * 32 + mi * 16 + (lane >> 2);
            float2 v0 = {c[0] + bd[n], c[1] + bd[n + 1]};
            float2 v1 = {c[2] + bd[n], c[3] + bd[n + 1]};
            *reinterpret_cast<float2*>(out + (size_t)r * FF + n) = v0;
            *reinterpret_cast<float2*>(out + (size_t)(r + 8) * FF + n) = v1;
        }
}

// ---------------- prep kernels -------------------------------------------------
__global__ void prep_wsum(const float* __restrict__ W, const float* __restrict__ U) {
    __shared__ float tl[32][33];
    const int n0 = blockIdx.x * 32, k0 = blockIdx.y * 32;
    const int tx = threadIdx.x, ty = threadIdx.y;
    const int n = n0 + tx;
    const int col = ((n & 3) << 10) | (n >> 2);
    for (int kk = ty; kk < 32; kk += 8)
        tl[tx][kk] = W[(size_t)(k0 + kk) * 4096 + col] + U[(size_t)(k0 + kk) * 4096 + col];
    __syncthreads();
    for (int nn = ty; nn < 32; nn += 8)
        g_wsum[(size_t)(n0 + nn) * 1024 + k0 + tx] = __float2half(tl[nn][tx]);
}

__global__ void prep_wcat(const float* __restrict__ W, const float* __restrict__ U) {
    __shared__ float tl[32][33];
    const int n0 = blockIdx.x * 32, k0 = blockIdx.y * 32;
    const int tx = threadIdx.x, ty = threadIdx.y;
    const int n = n0 + tx;
    const int col = ((n & 3) << 10) | (n >> 2);
    const float* S = (k0 < 1024) ? W : U;
    const int kbase = (k0 < 1024) ? k0 : (k0 - 1024);
    for (int kk = ty; kk < 32; kk += 8)
        tl[tx][kk] = S[(size_t)(kbase + kk) * 4096 + col];
    __syncthreads();
    for (int nn = ty; nn < 32; nn += 8)
        g_wcat[(size_t)(n0 + nn) * 2048 + k0 + tx] = __float2half(tl[nn][tx]);
}

__global__ void prep_wd(const float* __restrict__ Wd) {
    __shared__ float tl[32][33];
    const int n0 = blockIdx.x * 32, k0 = blockIdx.y * 32;
    const int tx = threadIdx.x, ty = threadIdx.y;
    for (int kk = ty; kk < 32; kk += 8)
        tl[tx][kk] = Wd[(size_t)(k0 + kk) * 512 + n0 + tx];
    __syncthreads();
    for (int nn = ty; nn < 32; nn += 8)
        g_wd[(size_t)(n0 + nn) * 1024 + k0 + tx] = __float2half(tl[nn][tx]);
}

__global__ void prep_xc(const float* __restrict__ x0, const float* __restrict__ h0) {
    const int i = blockIdx.x * blockDim.x + threadIdx.x;
    const int m = i >> 11, k = i & 2047;
    const float v = (k < 1024) ? x0[m * 1024 + k] : h0[m * 1024 + k - 1024];
    g_xcat[i] = __float2half(v);
}

// ---------------- launch --------------------------------------------------------
extern "C" void kernel_launch(void* const* d_in, const int* in_sizes, int n_in,
                              void* d_out, int out_size) {
    const float* x0 = (const float*)d_in[0];
    const float* h0 = (const float*)d_in[1];
    const float* c0 = (const float*)d_in[2];
    const float* W  = (const float*)d_in[3];
    const float* U  = (const float*)d_in[4];
    const float* bi = (const float*)d_in[5];
    const float* Wd = (const float*)d_in[6];
    const float* bd = (const float*)d_in[7];
    float* out = (float*)d_out;

    static bool attr_done = false;
    if (!attr_done) {
        cudaFuncSetAttribute(lstm_scan, cudaFuncAttributeMaxDynamicSharedMemorySize, SC_SMEM);
        cudaFuncSetAttribute(dense_mma, cudaFuncAttributeMaxDynamicSharedMemorySize, D_SMEM);
        attr_done = true;
    }

    void* p;
    cudaGetSymbolAddress(&p, g_wsum);  __half* wsum = (__half*)p;
    cudaGetSymbolAddress(&p, g_wcat);  __half* wcat = (__half*)p;
    cudaGetSymbolAddress(&p, g_xcat);  __half* xc   = (__half*)p;
    __half* xb0; __half* xb1;
    cudaGetSymbolAddress(&p, g_xa);    xb0 = (__half*)p;
    cudaGetSymbolAddress(&p, g_xb);    xb1 = (__half*)p;

    dim3 tb(32, 8);
    // order keeps lstm_scan in ncu's 4th-launch capture slot
    prep_wsum<<<dim3(128, 32), tb>>>(W, U);
    prep_wcat<<<dim3(128, 64), tb>>>(W, U);
    prep_xc<<<2048, 256>>>(x0, h0);

    lstm_scan<<<NCTA, 256, SC_SMEM>>>(xc, wcat, wsum, bi, c0, xb0, xb1);

    prep_wd<<<dim3(16, 32), tb>>>(Wd);
    dense_mma<<<dim3(4, 512), 256, D_SMEM>>>(bd, out);
}

// round 15
// speedup vs baseline: 1.0345x; 1.0345x over previous
#include <cuda_runtime.h>
#include <cuda_fp16.h>
#include <math.h>
#include <stdint.h>

#define BB 256
#define HH 1024
#define TT 128
#define FF 512

#define NCTA 128
#define NMT 4          // mtile groups
#define GRP_CTAS 32    // CTAs per group (all ntiles of one mtile)

// ---- scan kernel tiling: CTA 64(M) x 128(N), KC=64/stage, 3 stages ----
#define KC 64
#define SC_NSTG 3
#define SC_OFF_A 0
#define SC_OFF_B 8192
#define SC_STAGE 24576
#define SC_SMEM  (SC_NSTG * SC_STAGE)     // 73728

// ---- dense kernel tiling: KC=32, 4 stages ----
#define DKC 32
#define D_OFF_A  0
#define D_OFF_B  4096
#define D_STAGE  12288
#define D_SMEM   (4 * D_STAGE)            // 49152

// ---------------- device scratch ----------------------------------------------
__device__ __half g_wsum[4096 * 1024];      // [n=4j+g][k]
__device__ __half g_wcat[4096 * 2048];      // t=0: K = [W;U]
__device__ __half g_wd[512 * 1024];         // [f][k]
__device__ __half g_xcat[256 * 2048];       // [b][x0,h0]
__device__ __half g_xa[256 * 1024];         // ping
__device__ __half g_xb[256 * 1024];         // pong
__device__ __half g_seq[(size_t)BB * TT * HH];
__device__ unsigned g_bar_cnt[NMT * 32];    // per-mtile counters, 128B apart
__device__ unsigned g_bar_gen[NMT * 32];    // per-mtile generations, 128B apart

// ---------------- helpers -----------------------------------------------------
__device__ __forceinline__ uint32_t smem_u32(const void* p) {
    uint32_t a;
    asm("{ .reg .u64 t; cvta.to.shared.u64 t, %1; cvt.u32.u64 %0, t; }" : "=r"(a) : "l"(p));
    return a;
}
__device__ __forceinline__ uint32_t sw64(uint32_t o)  { return o ^ ((o >> 3) & 0x30); }
__device__ __forceinline__ uint32_t sw128(uint32_t o) { return o ^ ((o >> 3) & 0x70); }
__device__ __forceinline__ float tanh_(float x) {
    float y;
    asm("tanh.approx.f32 %0, %1;" : "=f"(y) : "f"(x));
    return y;
}
__device__ __forceinline__ float sigm(float x) {
    return 0.5f * tanh_(0.5f * x) + 0.5f;
}

#define CP_ASYNC16(sm, gp) \
    asm volatile("cp.async.cg.shared.global [%0], [%1], 16;" :: "r"(sm), "l"(gp) : "memory")
#define CP_COMMIT() asm volatile("cp.async.commit_group;" ::: "memory")
template <int N>
__device__ __forceinline__ void cp_wait() {
    asm volatile("cp.async.wait_group %0;" :: "n"(N) : "memory");
}

__device__ __forceinline__ void ldsm4(uint32_t* r, uint32_t addr) {
    asm volatile("ldmatrix.sync.aligned.m8n8.x4.shared.b16 {%0,%1,%2,%3}, [%4];"
                 : "=r"(r[0]), "=r"(r[1]), "=r"(r[2]), "=r"(r[3]) : "r"(addr));
}
__device__ __forceinline__ void mma16816(float* c, const uint32_t* a, uint32_t b0, uint32_t b1) {
    asm volatile("mma.sync.aligned.m16n8k16.row.col.f32.f16.f16.f32 "
                 "{%0,%1,%2,%3},{%4,%5,%6,%7},{%8,%9},{%0,%1,%2,%3};"
                 : "+f"(c[0]), "+f"(c[1]), "+f"(c[2]), "+f"(c[3])
                 : "r"(a[0]), "r"(a[1]), "r"(a[2]), "r"(a[3]), "r"(b0), "r"(b1));
}

// ---------------- per-mtile split barrier (32 CTAs per group) ------------------
// Step-t dependencies are mtile-local: CTA (m,n) only reads h rows produced by
// CTAs (m,*). Each group has its own counter + generation word (128B-padded).
__device__ __forceinline__ void bar_arrive(int mgrp) {
    __syncthreads();                          // CTA's stores ordered before arrival
    if (threadIdx.x == 0) {
        __threadfence();                      // release
        unsigned a = atomicAdd(&g_bar_cnt[mgrp * 32], 1u);
        if (a == GRP_CTAS - 1) {
            atomicExch(&g_bar_cnt[mgrp * 32], 0u);
            __threadfence();
            atomicAdd(&g_bar_gen[mgrp * 32], 1u);   // release the group
        }
    }
}
__device__ __forceinline__ void bar_wait(int mgrp, unsigned target) {
    if (threadIdx.x == 0) {
        volatile unsigned* pg = &g_bar_gen[mgrp * 32];
        while (*pg < target) {}
        __threadfence();                      // acquire
    }
    __syncthreads();
}

// ---------------- persistent LSTM scan kernel ---------------------------------
// grid 128 CTAs = 32 n-tiles (Tn=128, gate-interleaved) x 4 m-tiles (Tm=64).
// KC=64 chunks; per-mtile split barrier with B-prefetch during the wait.
#define HSPAD 36   // halves per staged h row (32 data + 4 pad)

__global__ __launch_bounds__(256)
void lstm_scan(const __half* __restrict__ xcat, const __half* __restrict__ wcat,
               const __half* __restrict__ wsum,
               const float* __restrict__ bias, const float* __restrict__ c0,
               __half* __restrict__ x0buf, __half* __restrict__ x1buf) {
    extern __shared__ char smem[];
    const uint32_t sbase = smem_u32(smem);
    __half* HS = reinterpret_cast<__half*>(smem);   // staging, aliases stage 0 A-region

    const int ntile = blockIdx.x & 31;
    const int mtile = blockIdx.x >> 5;              // == barrier group
    const int am0 = mtile * 64;
    const int bn0 = ntile * 128;
    const int j0 = ntile * 32;

    const int tid = threadIdx.x;
    const int lane = tid & 31, wid = tid >> 5;
    const int wm = wid & 1, wn = wid >> 1;
    const bool odd = lane & 1;
    const int lrow = lane & 15;
    const int lkb = (lane >> 4) * 16;

    int bmap[2], jmap[4];
#pragma unroll
    for (int mi = 0; mi < 2; ++mi)
        bmap[mi] = am0 + wm * 32 + mi * 16 + (lane >> 2) + (odd ? 8 : 0);
#pragma unroll
    for (int nt = 0; nt < 4; ++nt)
        jmap[nt] = j0 + wn * 8 + nt * 2 + ((lane & 3) >> 1);

    float b_i[4], b_f[4], b_g[4], b_o[4];
#pragma unroll
    for (int nt = 0; nt < 4; ++nt) {
        b_i[nt] = bias[jmap[nt]];
        b_f[nt] = bias[HH + jmap[nt]];
        b_g[nt] = bias[2 * HH + jmap[nt]];
        b_o[nt] = bias[3 * HH + jmap[nt]];
    }
    float creg[2][4];
#pragma unroll
    for (int mi = 0; mi < 2; ++mi)
#pragma unroll
        for (int nt = 0; nt < 4; ++nt)
            creg[mi][nt] = c0[bmap[mi] * HH + jmap[nt]];

    auto issueA = [&](const __half* A, int ldk, int s, int c) {
        const uint32_t st = sbase + s * SC_STAGE;
        const int k0 = c * KC;
#pragma unroll
        for (int it = 0; it < 2; ++it) {
            const int g = it * 256 + tid;
            const int r = g >> 3, q = g & 7;
            CP_ASYNC16(st + SC_OFF_A + sw128((uint32_t)(r * 128 + q * 16)),
                       A + (size_t)(am0 + r) * ldk + k0 + q * 8);
        }
        CP_COMMIT();
    };
    auto issueB = [&](const __half* B, int ldk, int s, int c) {
        const uint32_t st = sbase + s * SC_STAGE;
        const int k0 = c * KC;
#pragma unroll
        for (int it = 0; it < 4; ++it) {
            const int g = it * 256 + tid;
            const int r = g >> 3, q = g & 7;
            CP_ASYNC16(st + SC_OFF_B + sw128((uint32_t)(r * 128 + q * 16)),
                       B + (size_t)(bn0 + r) * ldk + k0 + q * 8);
        }
        CP_COMMIT();
    };
    auto issueAB = [&](const __half* A, const __half* B, int ldk, int s, int c) {
        const uint32_t st = sbase + s * SC_STAGE;
        const int k0 = c * KC;
#pragma unroll
        for (int it = 0; it < 2; ++it) {
            const int g = it * 256 + tid;
            const int r = g >> 3, q = g & 7;
            CP_ASYNC16(st + SC_OFF_A + sw128((uint32_t)(r * 128 + q * 16)),
                       A + (size_t)(am0 + r) * ldk + k0 + q * 8);
        }
#pragma unroll
        for (int it = 0; it < 4; ++it) {
            const int g = it * 256 + tid;
            const int r = g >> 3, q = g & 7;
            CP_ASYNC16(st + SC_OFF_B + sw128((uint32_t)(r * 128 + q * 16)),
                       B + (size_t)(bn0 + r) * ldk + k0 + q * 8);
        }
        CP_COMMIT();
    };
    auto mma_stage = [&](int s, float C[2][4][4]) {
        const uint32_t st = sbase + s * SC_STAGE;
#pragma unroll
        for (int h = 0; h < 4; ++h) {
            uint32_t ah[2][4], bh[2][4];
#pragma unroll
            for (int mi = 0; mi < 2; ++mi)
                ldsm4(ah[mi], st + SC_OFF_A +
                      sw128((uint32_t)((wm * 32 + mi * 16 + lrow) * 128 + h * 32 + lkb)));
#pragma unroll
            for (int nj = 0; nj < 2; ++nj)
                ldsm4(bh[nj], st + SC_OFF_B +
                      sw128((uint32_t)((wn * 32 + nj * 16 + lrow) * 128 + h * 32 + lkb)));
#pragma unroll
            for (int mi = 0; mi < 2; ++mi)
#pragma unroll
                for (int nt = 0; nt < 4; ++nt) {
                    const int gsel = nt >> 1, ssel = nt & 1;
                    mma16816(C[mi][nt], ah[mi], bh[gsel][ssel], bh[gsel][ssel + 2]);
                }
        }
    };

    const unsigned G = *(volatile unsigned*)&g_bar_gen[mtile * 32];
    unsigned tgt = G;

    for (int t = 0; t < TT; ++t) {
        __half* xnext = (t & 1) ? x1buf : x0buf;

        float C[2][4][4];
#pragma unroll
        for (int a = 0; a < 2; ++a)
#pragma unroll
            for (int bq = 0; bq < 4; ++bq)
#pragma unroll
                for (int d = 0; d < 4; ++d) C[a][bq][d] = 0.0f;

        if (t == 0) {
            const int nch = 2048 / KC;   // 32
            issueAB(xcat, wcat, 2048, 0, 0);
            issueAB(xcat, wcat, 2048, 1, 1);
            for (int c = 0; c < nch; ++c) {
                if (c < nch - 1) cp_wait<1>(); else cp_wait<0>();
                __syncthreads();
                mma_stage(c % SC_NSTG, C);
                if (c + 2 < nch) issueAB(xcat, wcat, 2048, (c + 2) % SC_NSTG, c + 2);
            }
        } else {
            const __half* A = (t & 1) ? x0buf : x1buf;
            const int nch = HH / KC;     // 16
            // B chunks 0,1 prefetched during the barrier wait; add A now.
            issueA(A, HH, 0, 0);
            issueA(A, HH, 1, 1);
            for (int c = 0; c < nch; ++c) {
                if (c < nch - 1) cp_wait<1>(); else cp_wait<0>();
                __syncthreads();
                mma_stage(c % SC_NSTG, C);
                if (c + 2 < nch) issueAB(A, wsum, HH, (c + 2) % SC_NSTG, c + 2);
            }
        }
        __syncthreads();   // all stages consumed before HS reuse

        // epilogue: gates, c in registers, h -> smem staging
#pragma unroll
        for (int mi = 0; mi < 2; ++mi)
#pragma unroll
            for (int nt = 0; nt < 4; ++nt) {
                float* c = C[mi][nt];
                const float t0 = __shfl_xor_sync(0xFFFFFFFFu, c[0], 1);
                const float t1 = __shfl_xor_sync(0xFFFFFFFFu, c[1], 1);
                const float t2 = __shfl_xor_sync(0xFFFFFFFFu, c[2], 1);
                const float t3 = __shfl_xor_sync(0xFFFFFFFFu, c[3], 1);
                float zi, zf, zg, zo;
                if (!odd) { zi = c[0]; zf = c[1]; zg = t0; zo = t1; }
                else      { zi = t2;  zf = t3;  zg = c[2]; zo = c[3]; }
                zi += b_i[nt]; zf += b_f[nt]; zg += b_g[nt]; zo += b_o[nt];
                const float cn = sigm(zf) * creg[mi][nt] + sigm(zi) * tanh_(zg);
                const float hn = sigm(zo) * tanh_(cn);
                creg[mi][nt] = cn;
                HS[(bmap[mi] - am0) * HSPAD + (jmap[nt] - j0)] = __float2half(hn);
            }
        __syncthreads();

        // coalesced copy-out: 64 rows x 64B
        {
            const int row = tid >> 2, q = tid & 3;
            const uint32_t* src = reinterpret_cast<const uint32_t*>(HS + row * HSPAD) + q * 4;
            uint4 v;
            v.x = src[0]; v.y = src[1]; v.z = src[2]; v.w = src[3];
            const int b = am0 + row;
            *reinterpret_cast<uint4*>(xnext + (size_t)b * HH + j0 + q * 8) = v;
            *reinterpret_cast<uint4*>(g_seq + ((size_t)b * TT + t) * HH + j0 + q * 8) = v;
        }

        if (t < TT - 1) {
            ++tgt;
            bar_arrive(mtile);                    // includes __syncthreads
            issueB(wsum, HH, 0, 0);               // prefetch next step's B during wait
            issueB(wsum, HH, 1, 1);               // (HS region untouched: B at +8KB)
            bar_wait(mtile, tgt);
        }
    }
}

// ---------------- dense emission (64x128, KC=32) -------------------------------
__device__ __forceinline__ void d_issue(uint32_t sbase, int s, int c,
                                        const __half* A, int am0,
                                        const __half* B, int bn0, int tid) {
    const uint32_t st = sbase + s * D_STAGE;
    const int k0 = c * DKC;
    const int ar = tid >> 2, ac = tid & 3;
    CP_ASYNC16(st + D_OFF_A + sw64((uint32_t)(ar * 64 + ac * 16)),
               A + (size_t)(am0 + ar) * HH + k0 + ac * 8);
#pragma unroll
    for (int it = 0; it < 2; ++it) {
        const int idx = it * 256 + tid;
        const int br = idx >> 2, bc = idx & 3;
        CP_ASYNC16(st + D_OFF_B + sw64((uint32_t)(br * 64 + bc * 16)),
                   B + (size_t)(bn0 + br) * HH + k0 + bc * 8);
    }
    CP_COMMIT();
}

__global__ __launch_bounds__(256)
void dense_mma(const float* __restrict__ bd, float* __restrict__ out) {
    extern __shared__ char smem[];
    const uint32_t sbase = smem_u32(smem);
    const int tid = threadIdx.x;
    const int lane = tid & 31, wid = tid >> 5;
    const int wm = wid & 1, wn = wid >> 1;
    const int lrow = lane & 15;
    const int lkb = (lane >> 4) * 16;

    float C[2][4][4];
#pragma unroll
    for (int a = 0; a < 2; ++a)
#pragma unroll
        for (int bq = 0; bq < 4; ++bq)
#pragma unroll
            for (int d = 0; d < 4; ++d) C[a][bq][d] = 0.0f;

    const int am0 = blockIdx.y * 64;
    const int bn0 = blockIdx.x * 128;
    const int nch = HH / DKC;

    d_issue(sbase, 0, 0, g_seq, am0, g_wd, bn0, tid);
    d_issue(sbase, 1, 1, g_seq, am0, g_wd, bn0, tid);
    d_issue(sbase, 2, 2, g_seq, am0, g_wd, bn0, tid);

    for (int c = 0; c < nch; ++c) {
        const int s = c & 3;
        if (c < nch - 2)       cp_wait<2>();
        else if (c == nch - 2) cp_wait<1>();
        else                   cp_wait<0>();
        __syncthreads();
        const uint32_t st = sbase + s * D_STAGE;
#pragma unroll
        for (int h = 0; h < 2; ++h) {
            uint32_t ah[2][4], bh[2][4];
#pragma unroll
            for (int mi = 0; mi < 2; ++mi)
                ldsm4(ah[mi], st + D_OFF_A + sw64((uint32_t)((wm * 32 + mi * 16 + lrow) * 64 + h * 32 + lkb)));
#pragma unroll
            for (int nj = 0; nj < 2; ++nj)
                ldsm4(bh[nj], st + D_OFF_B + sw64((uint32_t)((wn * 32 + nj * 16 + lrow) * 64 + h * 32 + lkb)));
#pragma unroll
            for (int mi = 0; mi < 2; ++mi)
#pragma unroll
                for (int nt = 0; nt < 4; ++nt) {
                    const int gsel = nt >> 1, ssel = nt & 1;
                    mma16816(C[mi][nt], ah[mi], bh[gsel][ssel], bh[gsel][ssel + 2]);
                }
        }
        if (c + 3 < nch)
            d_issue(sbase, (c + 3) & 3, c + 3, g_seq, am0, g_wd, bn0, tid);
    }

#pragma unroll
    for (int mi = 0; mi < 2; ++mi)
#pragma unroll
        for (int nt = 0; nt < 4; ++nt) {
            const float* c = C[mi][nt];
            const int n = bn0 + wn * 32 + nt * 8 + 2 * (lane & 3);
            const int r = am0 + wm * 32 + mi * 16 + (lane >> 2);
            float2 v0 = {c[0] + bd[n], c[1] + bd[n + 1]};
            float2 v1 = {c[2] + bd[n], c[3] + bd[n + 1]};
            *reinterpret_cast<float2*>(out + (size_t)r * FF + n) = v0;
            *reinterpret_cast<float2*>(out + (size_t)(r + 8) * FF + n) = v1;
        }
}

// ---------------- prep kernels -------------------------------------------------
__global__ void prep_wsum(const float* __restrict__ W, const float* __restrict__ U) {
    __shared__ float tl[32][33];
    const int n0 = blockIdx.x * 32, k0 = blockIdx.y * 32;
    const int tx = threadIdx.x, ty = threadIdx.y;
    const int n = n0 + tx;
    const int col = ((n & 3) << 10) | (n >> 2);
    for (int kk = ty; kk < 32; kk += 8)
        tl[tx][kk] = W[(size_t)(k0 + kk) * 4096 + col] + U[(size_t)(k0 + kk) * 4096 + col];
    __syncthreads();
    for (int nn = ty; nn < 32; nn += 8)
        g_wsum[(size_t)(n0 + nn) * 1024 + k0 + tx] = __float2half(tl[nn][tx]);
}

__global__ void prep_wcat(const float* __restrict__ W, const float* __restrict__ U) {
    __shared__ float tl[32][33];
    const int n0 = blockIdx.x * 32, k0 = blockIdx.y * 32;
    const int tx = threadIdx.x, ty = threadIdx.y;
    const int n = n0 + tx;
    const int col = ((n & 3) << 10) | (n >> 2);
    const float* S = (k0 < 1024) ? W : U;
    const int kbase = (k0 < 1024) ? k0 : (k0 - 1024);
    for (int kk = ty; kk < 32; kk += 8)
        tl[tx][kk] = S[(size_t)(kbase + kk) * 4096 + col];
    __syncthreads();
    for (int nn = ty; nn < 32; nn += 8)
        g_wcat[(size_t)(n0 + nn) * 2048 + k0 + tx] = __float2half(tl[nn][tx]);
}

__global__ void prep_wd(const float* __restrict__ Wd) {
    __shared__ float tl[32][33];
    const int n0 = blockIdx.x * 32, k0 = blockIdx.y * 32;
    const int tx = threadIdx.x, ty = threadIdx.y;
    for (int kk = ty; kk < 32; kk += 8)
        tl[tx][kk] = Wd[(size_t)(k0 + kk) * 512 + n0 + tx];
    __syncthreads();
    for (int nn = ty; nn < 32; nn += 8)
        g_wd[(size_t)(n0 + nn) * 1024 + k0 + tx] = __float2half(tl[nn][tx]);
}

__global__ void prep_xc(const float* __restrict__ x0, const float* __restrict__ h0) {
    const int i = blockIdx.x * blockDim.x + threadIdx.x;
    const int m = i >> 11, k = i & 2047;
    const float v = (k < 1024) ? x0[m * 1024 + k] : h0[m * 1024 + k - 1024];
    g_xcat[i] = __float2half(v);
}

// ---------------- launch --------------------------------------------------------
extern "C" void kernel_launch(void* const* d_in, const int* in_sizes, int n_in,
                              void* d_out, int out_size) {
    const float* x0 = (const float*)d_in[0];
    const float* h0 = (const float*)d_in[1];
    const float* c0 = (const float*)d_in[2];
    const float* W  = (const float*)d_in[3];
    const float* U  = (const float*)d_in[4];
    const float* bi = (const float*)d_in[5];
    const float* Wd = (const float*)d_in[6];
    const float* bd = (const float*)d_in[7];
    float* out = (float*)d_out;

    static bool attr_done = false;
    if (!attr_done) {
        cudaFuncSetAttribute(lstm_scan, cudaFuncAttributeMaxDynamicSharedMemorySize, SC_SMEM);
        cudaFuncSetAttribute(dense_mma, cudaFuncAttributeMaxDynamicSharedMemorySize, D_SMEM);
        attr_done = true;
    }

    void* p;
    cudaGetSymbolAddress(&p, g_wsum);  __half* wsum = (__half*)p;
    cudaGetSymbolAddress(&p, g_wcat);  __half* wcat = (__half*)p;
    cudaGetSymbolAddress(&p, g_xcat);  __half* xc   = (__half*)p;
    __half* xb0; __half* xb1;
    cudaGetSymbolAddress(&p, g_xa);    xb0 = (__half*)p;
    cudaGetSymbolAddress(&p, g_xb);    xb1 = (__half*)p;

    dim3 tb(32, 8);
    // order keeps lstm_scan in ncu's 4th-launch capture slot
    prep_wsum<<<dim3(128, 32), tb>>>(W, U);
    prep_wcat<<<dim3(128, 64), tb>>>(W, U);
    prep_xc<<<2048, 256>>>(x0, h0);

    lstm_scan<<<NCTA, 256, SC_SMEM>>>(xc, wcat, wsum, bi, c0, xb0, xb1);

    prep_wd<<<dim3(16, 32), tb>>>(Wd);
    dense_mma<<<dim3(4, 512), 256, D_SMEM>>>(bd, out);
}